// round 9
// baseline (speedup 1.0000x reference)
#include <cuda_runtime.h>
#include <cstdint>
#include <cstddef>

#define T_STEPS 4096
#define HD      512
#define NC      4880
#define G3      1536
#define CLUSTER_CTAS 16
#define JPC     32            // hidden indices per CTA

// ---------------- scratch (static device globals; no allocation) ----------------
__device__ float g_visit[(size_t)T_STEPS * HD];     // 8 MB
__device__ float g_gi[(size_t)T_STEPS * G3];        // 25 MB
__device__ float g_hs[(size_t)T_STEPS * HD];        // 8 MB (history for epilogue)
__device__ float g_logits[T_STEPS];
__device__ float g_alpha[T_STEPS];

// ---------------- generic fp32 SIMT GEMM: C[M,N] = A x B (+bias) ----------------
template <bool A_KMAJ, bool B_KMAJ, bool BIAS>
__global__ __launch_bounds__(256)
void gemm_kernel(const float* __restrict__ A, const float* __restrict__ B,
                 const float* __restrict__ bias, float* __restrict__ C,
                 int M, int N, int K, int lda, int ldb, int ldc)
{
    constexpr int BM = 128, BN = 64, BK = 16;
    __shared__ float As[BK][BM + 4];
    __shared__ float Bs[BK][BN + 4];

    const int tid = threadIdx.x;
    const int tx  = tid & 15;
    const int ty  = tid >> 4;
    const int m0  = blockIdx.y * BM;
    const int n0  = blockIdx.x * BN;

    float acc[8][4];
#pragma unroll
    for (int i = 0; i < 8; i++)
#pragma unroll
        for (int j = 0; j < 4; j++) acc[i][j] = 0.f;

    for (int k0 = 0; k0 < K; k0 += BK) {
        if (A_KMAJ) {
#pragma unroll
            for (int it = 0; it < 2; it++) {
                int idx = tid + it * 256;
                int kk  = idx >> 5;
                int mm4 = idx & 31;
                float4 v = *(const float4*)&A[(size_t)(k0 + kk) * lda + m0 + mm4 * 4];
                *(float4*)&As[kk][mm4 * 4] = v;
            }
        } else {
#pragma unroll
            for (int it = 0; it < 2; it++) {
                int idx = tid + it * 256;
                int mm  = idx >> 2;
                int k4  = idx & 3;
                float4 v = *(const float4*)&A[(size_t)(m0 + mm) * lda + k0 + k4 * 4];
                As[k4 * 4 + 0][mm] = v.x;
                As[k4 * 4 + 1][mm] = v.y;
                As[k4 * 4 + 2][mm] = v.z;
                As[k4 * 4 + 3][mm] = v.w;
            }
        }
        if (B_KMAJ) {
            int kk  = tid >> 4;
            int nn4 = tid & 15;
            float4 v = *(const float4*)&B[(size_t)(k0 + kk) * ldb + n0 + nn4 * 4];
            *(float4*)&Bs[kk][nn4 * 4] = v;
        } else {
            int nn = tid >> 2;
            int k4 = tid & 3;
            float4 v = *(const float4*)&B[(size_t)(nn + n0) * ldb + k0 + k4 * 4];
            Bs[k4 * 4 + 0][nn] = v.x;
            Bs[k4 * 4 + 1][nn] = v.y;
            Bs[k4 * 4 + 2][nn] = v.z;
            Bs[k4 * 4 + 3][nn] = v.w;
        }
        __syncthreads();

#pragma unroll
        for (int kk = 0; kk < BK; kk++) {
            float4 a0 = *(const float4*)&As[kk][ty * 8];
            float4 a1 = *(const float4*)&As[kk][ty * 8 + 4];
            float4 b0 = *(const float4*)&Bs[kk][tx * 4];
            float a[8] = {a0.x, a0.y, a0.z, a0.w, a1.x, a1.y, a1.z, a1.w};
            float b[4] = {b0.x, b0.y, b0.z, b0.w};
#pragma unroll
            for (int i = 0; i < 8; i++)
#pragma unroll
                for (int j = 0; j < 4; j++) acc[i][j] += a[i] * b[j];
        }
        __syncthreads();
    }

    float4 bv = make_float4(0.f, 0.f, 0.f, 0.f);
    if (BIAS) bv = *(const float4*)&bias[n0 + tx * 4];
#pragma unroll
    for (int i = 0; i < 8; i++) {
        int m = m0 + ty * 8 + i;
        float4 v;
        v.x = acc[i][0] + bv.x;
        v.y = acc[i][1] + bv.y;
        v.z = acc[i][2] + bv.z;
        v.w = acc[i][3] + bv.w;
        *(float4*)&C[(size_t)m * ldc + n0 + tx * 4] = v;
    }
}

// ---------------- cluster / PTX helpers ----------------
__device__ __forceinline__ uint32_t s2u(const void* p)
{
    return (uint32_t)__cvta_generic_to_shared(p);
}
__device__ __forceinline__ uint32_t mapa_rank(uint32_t a, uint32_t r)
{
    uint32_t d;
    asm("mapa.shared::cluster.u32 %0, %1, %2;" : "=r"(d) : "r"(a), "r"(r));
    return d;
}
__device__ __forceinline__ uint32_t ctarank()
{
    uint32_t r;
    asm("mov.u32 %0, %%cluster_ctarank;" : "=r"(r));
    return r;
}
__device__ __forceinline__ void st_cluster_f32(uint32_t addr, float v)
{
    asm volatile("st.shared::cluster.f32 [%0], %1;" :: "r"(addr), "f"(v) : "memory");
}
__device__ __forceinline__ void mbar_init(uint32_t addr, uint32_t count)
{
    asm volatile("mbarrier.init.shared.b64 [%0], %1;" :: "r"(addr), "r"(count) : "memory");
}
__device__ __forceinline__ void mbar_arrive_cluster(uint32_t addr)
{
    asm volatile("mbarrier.arrive.release.cluster.shared::cluster.b64 _, [%0];"
                 :: "r"(addr) : "memory");
}
// Bounded wait: ~500 rounds x 20us hint. Returns 1 on success, 0 on timeout
// (fall through -> loud wrong answer instead of a hung container).
__device__ __forceinline__ int mbar_wait_bounded(uint32_t addr, uint32_t parity)
{
    int ok;
    asm volatile(
        "{\n\t"
        ".reg .pred P;\n\t"
        ".reg .u32 c;\n\t"
        "mov.u32 c, 0;\n\t"
        "WL_%=:\n\t"
        "mbarrier.try_wait.parity.acquire.cluster.shared::cta.b64 P, [%1], %2, 20000;\n\t"
        "@P bra.uni WOK_%=;\n\t"
        "add.u32 c, c, 1;\n\t"
        "setp.lt.u32 P, c, 500;\n\t"
        "@P bra.uni WL_%=;\n\t"
        "mov.u32 %0, 0;\n\t"
        "bra.uni WD_%=;\n\t"
        "WOK_%=:\n\t"
        "mov.u32 %0, 1;\n\t"
        "WD_%=:\n\t"
        "}"
        : "=r"(ok) : "r"(addr), "r"(parity) : "memory");
    return ok;
}
__device__ __forceinline__ void cluster_sync_hw()
{
    asm volatile("barrier.cluster.arrive.aligned;" ::: "memory");
    asm volatile("barrier.cluster.wait.aligned;" ::: "memory");
}
// packed fp32x2 fma / add (sm_100+)
__device__ __forceinline__ void fma2(unsigned long long& acc,
                                     unsigned long long a, unsigned long long b)
{
    asm("fma.rn.f32x2 %0, %1, %2, %0;" : "+l"(acc) : "l"(a), "l"(b));
}
__device__ __forceinline__ void add2(unsigned long long& a, unsigned long long b)
{
    asm("add.rn.f32x2 %0, %0, %1;" : "+l"(a) : "l"(b));
}
__device__ __forceinline__ float2 unpk(unsigned long long v)
{
    return *reinterpret_cast<float2*>(&v);
}
__device__ __forceinline__ unsigned long long pk2(float x, float y)
{
    float2 t = make_float2(x, y);
    return *reinterpret_cast<unsigned long long*>(&t);
}
__device__ __forceinline__ float tanh_fast(float x)
{
    float e = __expf(2.f * x);
    return 1.f - 2.f / (e + 1.f);
}

// ---------------- GRU scan v8b: 16-CTA cluster, DSMEM + bounded mbarrier ------
__global__ __launch_bounds__(256, 1)
void gru_scan8_kernel(const float* __restrict__ W_hh, const float* __restrict__ b_hh,
                      const float* __restrict__ gi)
{
    __shared__ __align__(16) float h_s[2][HD];
    __shared__ __align__(8) unsigned long long mbar[2];

    const int tid  = threadIdx.x;
    const int w    = tid >> 5;
    const int lane = tid & 31;
    const int p    = lane & 7;          // h-segment index
    const int q    = lane >> 3;         // j-within-warp (group)
    const uint32_t r = ctarank();
    const int j    = (int)r * JPC + w * 4 + q;          // this group's hidden index
    const int jv   = (int)r * JPC + w * 4 + (lane & 3); // value this lane ships

    // --- weights into registers: 3 gate rows, 64-elem segment, packed f32x2 ---
    unsigned long long wr[32], wz[32], wn[32];
    {
        const unsigned long long* pr =
            (const unsigned long long*)(W_hh + (size_t)j * HD + p * 64);
        const unsigned long long* pz =
            (const unsigned long long*)(W_hh + (size_t)(HD + j) * HD + p * 64);
        const unsigned long long* pn =
            (const unsigned long long*)(W_hh + (size_t)(2 * HD + j) * HD + p * 64);
#pragma unroll
        for (int c = 0; c < 32; c++) { wr[c] = pr[c]; wz[c] = pz[c]; wn[c] = pn[c]; }
    }
    float bhr = 0.f, bhz = 0.f, bhn = 0.f;
    if (p == 0) {
        bhr = __ldg(b_hh + j);
        bhz = __ldg(b_hh + HD + j);
        bhn = __ldg(b_hh + 2 * HD + j);
    }

    // --- precompute remote addresses (2 peers x 2 buffers) ---
    const uint32_t pA = (uint32_t)(lane >> 2);        // 0..7
    const uint32_t pB = pA + 8;                       // 8..15
    uint32_t stA[2], stB[2], mbA[2], mbB[2];
#pragma unroll
    for (int b = 0; b < 2; b++) {
        uint32_t hloc = s2u(&h_s[b][jv]);
        uint32_t mloc = s2u(&mbar[b]);
        stA[b] = mapa_rank(hloc, pA);
        stB[b] = mapa_rank(hloc, pB);
        mbA[b] = mapa_rank(mloc, pA);
        mbB[b] = mapa_rank(mloc, pB);
    }
    const uint32_t mbl0 = s2u(&mbar[0]);
    const uint32_t mbl1 = s2u(&mbar[1]);

    // --- init: h_s[0]=0, mbarriers count=512 ---
    h_s[0][tid]       = 0.f;
    h_s[0][tid + 256] = 0.f;
    if (tid == 0) {
        mbar_init(mbl0, 512);
        mbar_init(mbl1, 512);
    }
    __syncthreads();
    cluster_sync_hw();    // all CTAs' mbarriers + zeroed buffers visible

    // gi for t=0 (group-lead lanes)
    float gr = 0.f, gz = 0.f, gn = 0.f;
    if (p == 0) {
        gr = __ldg(gi + j);
        gz = __ldg(gi + HD + j);
        gn = __ldg(gi + 2 * HD + j);
    }

    int ph0 = 0, ph1 = 0;

    for (int t = 0; t < T_STEPS; t++) {
        // prefetch next step's gi (overlaps compute + comm)
        float grn = 0.f, gzn = 0.f, gnn = 0.f;
        if (p == 0 && t + 1 < T_STEPS) {
            const float* gt = gi + (size_t)(t + 1) * G3;
            grn = __ldg(gt + j);
            gzn = __ldg(gt + HD + j);
            gnn = __ldg(gt + 2 * HD + j);
        }

        const int buf = t & 1;
        if (t > 0) {
            // wait for all 512 h_{t-1} values (HW-sleep mbarrier, bounded)
            if (buf) { mbar_wait_bounded(mbl1, (uint32_t)(ph1 & 1)); ph1++; }
            else     { mbar_wait_bounded(mbl0, (uint32_t)(ph0 & 1)); ph0++; }
        }

        // --- 3 gate dots over this lane's 64-elem h segment (packed f32x2) ---
        unsigned long long acc0 = 0ull, acc1 = 0ull, acc2 = 0ull;
        const unsigned long long* hp =
            (const unsigned long long*)&h_s[buf][p * 64];
#pragma unroll
        for (int c = 0; c < 32; c++) {
            unsigned long long hv = hp[c];
            fma2(acc0, wr[c], hv);
            fma2(acc1, wz[c], hv);
            fma2(acc2, wn[c], hv);
        }
        float2 a0 = unpk(acc0), a1 = unpk(acc1), a2 = unpk(acc2);
        float ar = a0.x + a0.y, az = a1.x + a1.y, an = a2.x + a2.y;

        // 3-level butterfly within the 8-lane group ((ar,az) packed + an)
        unsigned long long pkv = pk2(ar, az);
#pragma unroll
        for (int o = 1; o <= 4; o <<= 1) {
            unsigned long long po = __shfl_xor_sync(0xffffffffu, pkv, o);
            add2(pkv, po);
            an += __shfl_xor_sync(0xffffffffu, an, o);
        }
        float2 rz = unpk(pkv);
        ar = rz.x; az = rz.y;

        // gates on group-lead lanes
        float hn = 0.f;
        if (p == 0) {
            float hj = h_s[buf][j];
            float rr = 1.f / (1.f + __expf(-(gr + ar + bhr)));
            float zz = 1.f / (1.f + __expf(-(gz + az + bhz)));
            float nv = tanh_fast(gn + rr * (an + bhn));
            hn = (1.f - zz) * nv + zz * hj;
            g_hs[(size_t)t * HD + j] = hn;     // history (off critical path)
        }
        // broadcast: lane l ships value (l&3), produced on lane (l&3)*8
        float hn_all = __shfl_sync(0xffffffffu, hn, (lane & 3) * 8);

        if (t + 1 < T_STEPS) {
            const int nb = (t + 1) & 1;
            st_cluster_f32(stA[nb], hn_all);
            st_cluster_f32(stB[nb], hn_all);
            mbar_arrive_cluster(mbA[nb]);
            mbar_arrive_cluster(mbB[nb]);
        }

        gr = grn; gz = gzn; gn = gnn;
    }

    cluster_sync_hw();
}

// ---------------- logits[t] = dot(hs[t], w_att) ----------------
__global__ __launch_bounds__(256)
void logits_kernel(const float* __restrict__ w_att)
{
    __shared__ float watt[HD];
    const int tid  = threadIdx.x;
    const int w    = tid >> 5;
    const int lane = tid & 31;
    watt[tid]       = w_att[tid];
    watt[tid + 256] = w_att[tid + 256];
    __syncthreads();

    int t = blockIdx.x * 8 + w;
    const float* h = g_hs + (size_t)t * HD;
    float acc = 0.f;
    int base = lane * 16;
#pragma unroll
    for (int i = 0; i < 16; i += 4) {
        float4 hv = *(const float4*)&h[base + i];
        float4 wv = *(const float4*)&watt[base + i];
        acc += hv.x * wv.x + hv.y * wv.y + hv.z * wv.z + hv.w * wv.w;
    }
#pragma unroll
    for (int off = 16; off > 0; off >>= 1)
        acc += __shfl_down_sync(0xffffffffu, acc, off);
    if (lane == 0) g_logits[t] = acc;
}

// ---------------- softmax over 4096 logits; also zero d_out ----------------
__global__ __launch_bounds__(1024)
void softmax_kernel(float* __restrict__ out)
{
    __shared__ float red[32];
    const int tid  = threadIdx.x;
    const int lane = tid & 31;
    const int wrp  = tid >> 5;

    float m = -1e30f;
    for (int i = tid; i < T_STEPS; i += 1024) m = fmaxf(m, g_logits[i]);
#pragma unroll
    for (int o = 16; o > 0; o >>= 1) m = fmaxf(m, __shfl_xor_sync(0xffffffffu, m, o));
    if (lane == 0) red[wrp] = m;
    __syncthreads();
    if (wrp == 0) {
        float v = red[lane];
#pragma unroll
        for (int o = 16; o > 0; o >>= 1) v = fmaxf(v, __shfl_xor_sync(0xffffffffu, v, o));
        if (lane == 0) red[0] = v;
    }
    __syncthreads();
    m = red[0];
    __syncthreads();

    float s = 0.f;
    for (int i = tid; i < T_STEPS; i += 1024) {
        float e = __expf(g_logits[i] - m);
        g_alpha[i] = e;
        s += e;
    }
#pragma unroll
    for (int o = 16; o > 0; o >>= 1) s += __shfl_xor_sync(0xffffffffu, s, o);
    if (lane == 0) red[wrp] = s;
    __syncthreads();
    if (wrp == 0) {
        float v = red[lane];
#pragma unroll
        for (int o = 16; o > 0; o >>= 1) v += __shfl_xor_sync(0xffffffffu, v, o);
        if (lane == 0) red[0] = v;
    }
    __syncthreads();
    float inv = 1.f / red[0];
    for (int i = tid; i < T_STEPS; i += 1024) g_alpha[i] *= inv;

    if (tid < HD) out[tid] = 0.f;
}

// ---------------- out[d] += sum_t alpha[t] * hs[t][d] ----------------
__global__ __launch_bounds__(256)
void wsum_kernel(float* __restrict__ out)
{
    const int tid = threadIdx.x;
    const int d   = tid * 2;
    float ax = 0.f, ay = 0.f;
    int t0 = blockIdx.x * 64;
#pragma unroll 4
    for (int tt = 0; tt < 64; tt++) {
        int t = t0 + tt;
        float a = g_alpha[t];
        float2 hv = *(const float2*)&g_hs[(size_t)t * HD + d];
        ax += a * hv.x;
        ay += a * hv.y;
    }
    atomicAdd(out + d, ax);
    atomicAdd(out + d + 1, ay);
}

// ---------------- launcher ----------------
extern "C" void kernel_launch(void* const* d_in, const int* in_sizes, int n_in,
                              void* d_out, int out_size)
{
    const float* H     = (const float*)d_in[0];
    // d_in[1] = TE (unused)
    const float* X_emb = (const float*)d_in[2];
    const float* W_ih  = (const float*)d_in[3];
    const float* W_hh  = (const float*)d_in[4];
    const float* b_ih  = (const float*)d_in[5];
    const float* b_hh  = (const float*)d_in[6];
    const float* w_att = (const float*)d_in[7];
    float* out = (float*)d_out;

    float* visit; float* gi;
    cudaGetSymbolAddress((void**)&visit, g_visit);
    cudaGetSymbolAddress((void**)&gi, g_gi);

    // 1) visit_emb[4096,512] = H^T @ X_emb
    {
        dim3 grid(HD / 64, T_STEPS / 128);
        gemm_kernel<true, true, false><<<grid, 256>>>(
            H, X_emb, nullptr, visit, T_STEPS, HD, NC, T_STEPS, HD, HD);
    }
    // 2) gi[4096,1536] = visit_emb @ W_ih^T + b_ih
    {
        dim3 grid(G3 / 64, T_STEPS / 128);
        gemm_kernel<false, false, true><<<grid, 256>>>(
            visit, W_ih, b_ih, gi, T_STEPS, G3, HD, HD, HD, G3);
    }
    // 3) sequential GRU scan: one 16-CTA cluster, DSMEM + bounded mbarrier
    {
        static int attr_set = 0;
        if (!attr_set) {
            cudaFuncSetAttribute(gru_scan8_kernel,
                                 cudaFuncAttributeNonPortableClusterSizeAllowed, 1);
            attr_set = 1;
        }
        cudaLaunchConfig_t cfg = {};
        cfg.gridDim  = dim3(CLUSTER_CTAS, 1, 1);
        cfg.blockDim = dim3(256, 1, 1);
        cfg.dynamicSmemBytes = 0;
        cfg.stream = 0;
        cudaLaunchAttribute attrs[1];
        attrs[0].id = cudaLaunchAttributeClusterDimension;
        attrs[0].val.clusterDim.x = CLUSTER_CTAS;
        attrs[0].val.clusterDim.y = 1;
        attrs[0].val.clusterDim.z = 1;
        cfg.attrs = attrs;
        cfg.numAttrs = 1;
        cudaLaunchKernelEx(&cfg, gru_scan8_kernel, W_hh, b_hh, (const float*)gi);
    }
    // 4) attention logits
    logits_kernel<<<T_STEPS / 8, 256>>>(w_att);
    // 5) softmax (+ zero out)
    softmax_kernel<<<1, 1024>>>(out);
    // 6) weighted sum
    wsum_kernel<<<T_STEPS / 64, 256>>>(out);
}

// round 10
// speedup vs baseline: 1.0440x; 1.0440x over previous
#include <cuda_runtime.h>
#include <cstdint>
#include <cstddef>

#define T_STEPS 4096
#define HD      512
#define NC      4880
#define G3      1536
#define CLUSTER_CTAS 16
#define JPC     32            // hidden indices per CTA

// ---------------- scratch (static device globals; no allocation) ----------------
__device__ float g_visit[(size_t)T_STEPS * HD];     // 8 MB
__device__ float g_gi[(size_t)T_STEPS * G3];        // 25 MB
__device__ float g_hs[(size_t)T_STEPS * HD];        // 8 MB (history for epilogue)
__device__ float g_logits[T_STEPS];
__device__ float g_alpha[T_STEPS];

// ---------------- generic fp32 SIMT GEMM: C[M,N] = A x B (+bias) ----------------
template <bool A_KMAJ, bool B_KMAJ, bool BIAS>
__global__ __launch_bounds__(256)
void gemm_kernel(const float* __restrict__ A, const float* __restrict__ B,
                 const float* __restrict__ bias, float* __restrict__ C,
                 int M, int N, int K, int lda, int ldb, int ldc)
{
    constexpr int BM = 128, BN = 64, BK = 16;
    __shared__ float As[BK][BM + 4];
    __shared__ float Bs[BK][BN + 4];

    const int tid = threadIdx.x;
    const int tx  = tid & 15;
    const int ty  = tid >> 4;
    const int m0  = blockIdx.y * BM;
    const int n0  = blockIdx.x * BN;

    float acc[8][4];
#pragma unroll
    for (int i = 0; i < 8; i++)
#pragma unroll
        for (int j = 0; j < 4; j++) acc[i][j] = 0.f;

    for (int k0 = 0; k0 < K; k0 += BK) {
        if (A_KMAJ) {
#pragma unroll
            for (int it = 0; it < 2; it++) {
                int idx = tid + it * 256;
                int kk  = idx >> 5;
                int mm4 = idx & 31;
                float4 v = *(const float4*)&A[(size_t)(k0 + kk) * lda + m0 + mm4 * 4];
                *(float4*)&As[kk][mm4 * 4] = v;
            }
        } else {
#pragma unroll
            for (int it = 0; it < 2; it++) {
                int idx = tid + it * 256;
                int mm  = idx >> 2;
                int k4  = idx & 3;
                float4 v = *(const float4*)&A[(size_t)(m0 + mm) * lda + k0 + k4 * 4];
                As[k4 * 4 + 0][mm] = v.x;
                As[k4 * 4 + 1][mm] = v.y;
                As[k4 * 4 + 2][mm] = v.z;
                As[k4 * 4 + 3][mm] = v.w;
            }
        }
        if (B_KMAJ) {
            int kk  = tid >> 4;
            int nn4 = tid & 15;
            float4 v = *(const float4*)&B[(size_t)(k0 + kk) * ldb + n0 + nn4 * 4];
            *(float4*)&Bs[kk][nn4 * 4] = v;
        } else {
            int nn = tid >> 2;
            int k4 = tid & 3;
            float4 v = *(const float4*)&B[(size_t)(nn + n0) * ldb + k0 + k4 * 4];
            Bs[k4 * 4 + 0][nn] = v.x;
            Bs[k4 * 4 + 1][nn] = v.y;
            Bs[k4 * 4 + 2][nn] = v.z;
            Bs[k4 * 4 + 3][nn] = v.w;
        }
        __syncthreads();

#pragma unroll
        for (int kk = 0; kk < BK; kk++) {
            float4 a0 = *(const float4*)&As[kk][ty * 8];
            float4 a1 = *(const float4*)&As[kk][ty * 8 + 4];
            float4 b0 = *(const float4*)&Bs[kk][tx * 4];
            float a[8] = {a0.x, a0.y, a0.z, a0.w, a1.x, a1.y, a1.z, a1.w};
            float b[4] = {b0.x, b0.y, b0.z, b0.w};
#pragma unroll
            for (int i = 0; i < 8; i++)
#pragma unroll
                for (int j = 0; j < 4; j++) acc[i][j] += a[i] * b[j];
        }
        __syncthreads();
    }

    float4 bv = make_float4(0.f, 0.f, 0.f, 0.f);
    if (BIAS) bv = *(const float4*)&bias[n0 + tx * 4];
#pragma unroll
    for (int i = 0; i < 8; i++) {
        int m = m0 + ty * 8 + i;
        float4 v;
        v.x = acc[i][0] + bv.x;
        v.y = acc[i][1] + bv.y;
        v.z = acc[i][2] + bv.z;
        v.w = acc[i][3] + bv.w;
        *(float4*)&C[(size_t)m * ldc + n0 + tx * 4] = v;
    }
}

// ---------------- cluster / PTX helpers ----------------
__device__ __forceinline__ uint32_t s2u(const void* p)
{
    return (uint32_t)__cvta_generic_to_shared(p);
}
__device__ __forceinline__ uint32_t mapa_rank(uint32_t a, uint32_t r)
{
    uint32_t d;
    asm("mapa.shared::cluster.u32 %0, %1, %2;" : "=r"(d) : "r"(a), "r"(r));
    return d;
}
__device__ __forceinline__ uint32_t ctarank()
{
    uint32_t r;
    asm("mov.u32 %0, %%cluster_ctarank;" : "=r"(r));
    return r;
}
__device__ __forceinline__ void st_cluster_f32(uint32_t addr, float v)
{
    asm volatile("st.shared::cluster.f32 [%0], %1;" :: "r"(addr), "f"(v) : "memory");
}
__device__ __forceinline__ void mbar_init(uint32_t addr, uint32_t count)
{
    asm volatile("mbarrier.init.shared.b64 [%0], %1;" :: "r"(addr), "r"(count) : "memory");
}
__device__ __forceinline__ void mbar_arrive_cluster(uint32_t addr)
{
    asm volatile("mbarrier.arrive.release.cluster.shared::cluster.b64 _, [%0];"
                 :: "r"(addr) : "memory");
}
__device__ __forceinline__ void fence_cluster()
{
    asm volatile("fence.acq_rel.cluster;" ::: "memory");
}
// Bounded wait: ~500 rounds x 20us hint. Returns 1 on success, 0 on timeout
// (fall through -> loud wrong answer instead of a hung container).
__device__ __forceinline__ int mbar_wait_bounded(uint32_t addr, uint32_t parity)
{
    int ok;
    asm volatile(
        "{\n\t"
        ".reg .pred P;\n\t"
        ".reg .u32 c;\n\t"
        "mov.u32 c, 0;\n\t"
        "WL_%=:\n\t"
        "mbarrier.try_wait.parity.acquire.cluster.shared::cta.b64 P, [%1], %2, 20000;\n\t"
        "@P bra.uni WOK_%=;\n\t"
        "add.u32 c, c, 1;\n\t"
        "setp.lt.u32 P, c, 500;\n\t"
        "@P bra.uni WL_%=;\n\t"
        "mov.u32 %0, 0;\n\t"
        "bra.uni WD_%=;\n\t"
        "WOK_%=:\n\t"
        "mov.u32 %0, 1;\n\t"
        "WD_%=:\n\t"
        "}"
        : "=r"(ok) : "r"(addr), "r"(parity) : "memory");
    return ok;
}
__device__ __forceinline__ void cluster_sync_hw()
{
    asm volatile("barrier.cluster.arrive.aligned;" ::: "memory");
    asm volatile("barrier.cluster.wait.aligned;" ::: "memory");
}
// packed fp32x2 fma / add (sm_100+)
__device__ __forceinline__ void fma2(unsigned long long& acc,
                                     unsigned long long a, unsigned long long b)
{
    asm("fma.rn.f32x2 %0, %1, %2, %0;" : "+l"(acc) : "l"(a), "l"(b));
}
__device__ __forceinline__ void add2(unsigned long long& a, unsigned long long b)
{
    asm("add.rn.f32x2 %0, %0, %1;" : "+l"(a) : "l"(b));
}
__device__ __forceinline__ float2 unpk(unsigned long long v)
{
    return *reinterpret_cast<float2*>(&v);
}
__device__ __forceinline__ unsigned long long pk2(float x, float y)
{
    float2 t = make_float2(x, y);
    return *reinterpret_cast<unsigned long long*>(&t);
}
__device__ __forceinline__ float tanh_fast(float x)
{
    float e = __expf(2.f * x);
    return 1.f - 2.f / (e + 1.f);
}

// ---------------- GRU scan v8c: cluster DSMEM, AGGREGATED arrivals ------------
// Identical dataflow to v8b (protocol validated: rel_err 1.5e-7) with ONE
// change: signaling. v8b sent 2 release-arrives per lane -> 1024 arrives/step
// landing on each CTA's single mbarrier word (SMEM-atomic serialization ~32
// cyc/warp => ~thousands of cycles/step). v8c: all lanes issue their 2 remote
// data stores, __syncthreads, fence.acq_rel.cluster (cumulativity orders the
// whole CTA's stores), then threads 0-15 each send ONE arrive to rank tid.
// mbarrier count 1024 -> 16 per step.
__global__ __launch_bounds__(256, 1)
void gru_scan8_kernel(const float* __restrict__ W_hh, const float* __restrict__ b_hh,
                      const float* __restrict__ gi)
{
    __shared__ __align__(16) float h_s[2][HD];
    __shared__ __align__(8) unsigned long long mbar[2];

    const int tid  = threadIdx.x;
    const int w    = tid >> 5;
    const int lane = tid & 31;
    const int p    = lane & 7;          // h-segment index
    const int q    = lane >> 3;         // j-within-warp (group)
    const uint32_t r = ctarank();
    const int j    = (int)r * JPC + w * 4 + q;          // this group's hidden index
    const int jv   = (int)r * JPC + w * 4 + (lane & 3); // value this lane ships

    // --- weights into registers: 3 gate rows, 64-elem segment, packed f32x2 ---
    unsigned long long wr[32], wz[32], wn[32];
    {
        const unsigned long long* pr =
            (const unsigned long long*)(W_hh + (size_t)j * HD + p * 64);
        const unsigned long long* pz =
            (const unsigned long long*)(W_hh + (size_t)(HD + j) * HD + p * 64);
        const unsigned long long* pn =
            (const unsigned long long*)(W_hh + (size_t)(2 * HD + j) * HD + p * 64);
#pragma unroll
        for (int c = 0; c < 32; c++) { wr[c] = pr[c]; wz[c] = pz[c]; wn[c] = pn[c]; }
    }
    float bhr = 0.f, bhz = 0.f, bhn = 0.f;
    if (p == 0) {
        bhr = __ldg(b_hh + j);
        bhz = __ldg(b_hh + HD + j);
        bhn = __ldg(b_hh + 2 * HD + j);
    }

    // --- precompute remote data addresses (2 peers x 2 buffers) ---
    const uint32_t pA = (uint32_t)(lane >> 2);        // 0..7
    const uint32_t pB = pA + 8;                       // 8..15
    uint32_t stA[2], stB[2];
#pragma unroll
    for (int b = 0; b < 2; b++) {
        uint32_t hloc = s2u(&h_s[b][jv]);
        stA[b] = mapa_rank(hloc, pA);
        stB[b] = mapa_rank(hloc, pB);
    }
    // signal addresses: thread tid<16 arrives at rank tid's mbar[b]
    uint32_t mbR[2] = {0u, 0u};
    if (tid < 16) {
        mbR[0] = mapa_rank(s2u(&mbar[0]), (uint32_t)tid);
        mbR[1] = mapa_rank(s2u(&mbar[1]), (uint32_t)tid);
    }
    const uint32_t mbl0 = s2u(&mbar[0]);
    const uint32_t mbl1 = s2u(&mbar[1]);

    // --- init: h_s[0]=0, mbarriers count=16 (one aggregated arrive per CTA) ---
    h_s[0][tid]       = 0.f;
    h_s[0][tid + 256] = 0.f;
    if (tid == 0) {
        mbar_init(mbl0, CLUSTER_CTAS);
        mbar_init(mbl1, CLUSTER_CTAS);
    }
    __syncthreads();
    cluster_sync_hw();    // all CTAs' mbarriers + zeroed buffers visible

    // gi for t=0 (group-lead lanes)
    float gr = 0.f, gz = 0.f, gn = 0.f;
    if (p == 0) {
        gr = __ldg(gi + j);
        gz = __ldg(gi + HD + j);
        gn = __ldg(gi + 2 * HD + j);
    }

    int ph0 = 0, ph1 = 0;

    for (int t = 0; t < T_STEPS; t++) {
        // prefetch next step's gi (overlaps compute + comm)
        float grn = 0.f, gzn = 0.f, gnn = 0.f;
        if (p == 0 && t + 1 < T_STEPS) {
            const float* gt = gi + (size_t)(t + 1) * G3;
            grn = __ldg(gt + j);
            gzn = __ldg(gt + HD + j);
            gnn = __ldg(gt + 2 * HD + j);
        }

        const int buf = t & 1;
        if (t > 0) {
            // wait for all 16 CTAs' aggregated arrivals for h_{t-1}
            if (buf) { mbar_wait_bounded(mbl1, (uint32_t)(ph1 & 1)); ph1++; }
            else     { mbar_wait_bounded(mbl0, (uint32_t)(ph0 & 1)); ph0++; }
        }

        // --- 3 gate dots over this lane's 64-elem h segment (packed f32x2) ---
        unsigned long long acc0 = 0ull, acc1 = 0ull, acc2 = 0ull;
        const unsigned long long* hp =
            (const unsigned long long*)&h_s[buf][p * 64];
#pragma unroll
        for (int c = 0; c < 32; c++) {
            unsigned long long hv = hp[c];
            fma2(acc0, wr[c], hv);
            fma2(acc1, wz[c], hv);
            fma2(acc2, wn[c], hv);
        }
        float2 a0 = unpk(acc0), a1 = unpk(acc1), a2 = unpk(acc2);
        float ar = a0.x + a0.y, az = a1.x + a1.y, an = a2.x + a2.y;

        // 3-level butterfly within the 8-lane group ((ar,az) packed + an)
        unsigned long long pkv = pk2(ar, az);
#pragma unroll
        for (int o = 1; o <= 4; o <<= 1) {
            unsigned long long po = __shfl_xor_sync(0xffffffffu, pkv, o);
            add2(pkv, po);
            an += __shfl_xor_sync(0xffffffffu, an, o);
        }
        float2 rz = unpk(pkv);
        ar = rz.x; az = rz.y;

        // gates on group-lead lanes
        float hn = 0.f;
        if (p == 0) {
            float hj = h_s[buf][j];
            float rr = 1.f / (1.f + __expf(-(gr + ar + bhr)));
            float zz = 1.f / (1.f + __expf(-(gz + az + bhz)));
            float nv = tanh_fast(gn + rr * (an + bhn));
            hn = (1.f - zz) * nv + zz * hj;
            g_hs[(size_t)t * HD + j] = hn;     // history (off critical path)
        }
        // broadcast: lane l ships value (l&3), produced on lane (l&3)*8
        float hn_all = __shfl_sync(0xffffffffu, hn, (lane & 3) * 8);

        if (t + 1 < T_STEPS) {
            const int nb = (t + 1) & 1;
            // data: each lane covers one (value, rank) pair per half-cluster
            st_cluster_f32(stA[nb], hn_all);
            st_cluster_f32(stB[nb], hn_all);
            // aggregate signal: whole CTA's stores ordered, then 16 arrives
            __syncthreads();
            if (tid < 16) {
                fence_cluster();
                mbar_arrive_cluster(mbR[nb]);
            }
        }

        gr = grn; gz = gzn; gn = gnn;
    }

    cluster_sync_hw();
}

// ---------------- logits[t] = dot(hs[t], w_att) ----------------
__global__ __launch_bounds__(256)
void logits_kernel(const float* __restrict__ w_att)
{
    __shared__ float watt[HD];
    const int tid  = threadIdx.x;
    const int w    = tid >> 5;
    const int lane = tid & 31;
    watt[tid]       = w_att[tid];
    watt[tid + 256] = w_att[tid + 256];
    __syncthreads();

    int t = blockIdx.x * 8 + w;
    const float* h = g_hs + (size_t)t * HD;
    float acc = 0.f;
    int base = lane * 16;
#pragma unroll
    for (int i = 0; i < 16; i += 4) {
        float4 hv = *(const float4*)&h[base + i];
        float4 wv = *(const float4*)&watt[base + i];
        acc += hv.x * wv.x + hv.y * wv.y + hv.z * wv.z + hv.w * wv.w;
    }
#pragma unroll
    for (int off = 16; off > 0; off >>= 1)
        acc += __shfl_down_sync(0xffffffffu, acc, off);
    if (lane == 0) g_logits[t] = acc;
}

// ---------------- softmax over 4096 logits; also zero d_out ----------------
__global__ __launch_bounds__(1024)
void softmax_kernel(float* __restrict__ out)
{
    __shared__ float red[32];
    const int tid  = threadIdx.x;
    const int lane = tid & 31;
    const int wrp  = tid >> 5;

    float m = -1e30f;
    for (int i = tid; i < T_STEPS; i += 1024) m = fmaxf(m, g_logits[i]);
#pragma unroll
    for (int o = 16; o > 0; o >>= 1) m = fmaxf(m, __shfl_xor_sync(0xffffffffu, m, o));
    if (lane == 0) red[wrp] = m;
    __syncthreads();
    if (wrp == 0) {
        float v = red[lane];
#pragma unroll
        for (int o = 16; o > 0; o >>= 1) v = fmaxf(v, __shfl_xor_sync(0xffffffffu, v, o));
        if (lane == 0) red[0] = v;
    }
    __syncthreads();
    m = red[0];
    __syncthreads();

    float s = 0.f;
    for (int i = tid; i < T_STEPS; i += 1024) {
        float e = __expf(g_logits[i] - m);
        g_alpha[i] = e;
        s += e;
    }
#pragma unroll
    for (int o = 16; o > 0; o >>= 1) s += __shfl_xor_sync(0xffffffffu, s, o);
    if (lane == 0) red[wrp] = s;
    __syncthreads();
    if (wrp == 0) {
        float v = red[lane];
#pragma unroll
        for (int o = 16; o > 0; o >>= 1) v += __shfl_xor_sync(0xffffffffu, v, o);
        if (lane == 0) red[0] = v;
    }
    __syncthreads();
    float inv = 1.f / red[0];
    for (int i = tid; i < T_STEPS; i += 1024) g_alpha[i] *= inv;

    if (tid < HD) out[tid] = 0.f;
}

// ---------------- out[d] += sum_t alpha[t] * hs[t][d] ----------------
__global__ __launch_bounds__(256)
void wsum_kernel(float* __restrict__ out)
{
    const int tid = threadIdx.x;
    const int d   = tid * 2;
    float ax = 0.f, ay = 0.f;
    int t0 = blockIdx.x * 64;
#pragma unroll 4
    for (int tt = 0; tt < 64; tt++) {
        int t = t0 + tt;
        float a = g_alpha[t];
        float2 hv = *(const float2*)&g_hs[(size_t)t * HD + d];
        ax += a * hv.x;
        ay += a * hv.y;
    }
    atomicAdd(out + d, ax);
    atomicAdd(out + d + 1, ay);
}

// ---------------- launcher ----------------
extern "C" void kernel_launch(void* const* d_in, const int* in_sizes, int n_in,
                              void* d_out, int out_size)
{
    const float* H     = (const float*)d_in[0];
    // d_in[1] = TE (unused)
    const float* X_emb = (const float*)d_in[2];
    const float* W_ih  = (const float*)d_in[3];
    const float* W_hh  = (const float*)d_in[4];
    const float* b_ih  = (const float*)d_in[5];
    const float* b_hh  = (const float*)d_in[6];
    const float* w_att = (const float*)d_in[7];
    float* out = (float*)d_out;

    float* visit; float* gi;
    cudaGetSymbolAddress((void**)&visit, g_visit);
    cudaGetSymbolAddress((void**)&gi, g_gi);

    // 1) visit_emb[4096,512] = H^T @ X_emb
    {
        dim3 grid(HD / 64, T_STEPS / 128);
        gemm_kernel<true, true, false><<<grid, 256>>>(
            H, X_emb, nullptr, visit, T_STEPS, HD, NC, T_STEPS, HD, HD);
    }
    // 2) gi[4096,1536] = visit_emb @ W_ih^T + b_ih
    {
        dim3 grid(G3 / 64, T_STEPS / 128);
        gemm_kernel<false, false, true><<<grid, 256>>>(
            visit, W_ih, b_ih, gi, T_STEPS, G3, HD, HD, HD, G3);
    }
    // 3) sequential GRU scan: one 16-CTA cluster, DSMEM + aggregated arrivals
    {
        cudaFuncSetAttribute(gru_scan8_kernel,
                             cudaFuncAttributeNonPortableClusterSizeAllowed, 1);
        cudaLaunchConfig_t cfg = {};
        cfg.gridDim  = dim3(CLUSTER_CTAS, 1, 1);
        cfg.blockDim = dim3(256, 1, 1);
        cfg.dynamicSmemBytes = 0;
        cfg.stream = 0;
        cudaLaunchAttribute attrs[1];
        attrs[0].id = cudaLaunchAttributeClusterDimension;
        attrs[0].val.clusterDim.x = CLUSTER_CTAS;
        attrs[0].val.clusterDim.y = 1;
        attrs[0].val.clusterDim.z = 1;
        cfg.attrs = attrs;
        cfg.numAttrs = 1;
        cudaLaunchKernelEx(&cfg, gru_scan8_kernel, W_hh, b_hh, (const float*)gi);
    }
    // 4) attention logits
    logits_kernel<<<T_STEPS / 8, 256>>>(w_att);
    // 5) softmax (+ zero out)
    softmax_kernel<<<1, 1024>>>(out);
    // 6) weighted sum
    wsum_kernel<<<T_STEPS / 64, 256>>>(out);
}

// round 11
// speedup vs baseline: 1.7730x; 1.6982x over previous
#include <cuda_runtime.h>
#include <cstdint>
#include <cstddef>

#define T_STEPS 4096
#define HD      512
#define NC      4880
#define G3      1536
#define NCTAS   64

// ---------------- scratch (static device globals; no allocation) ----------------
__device__ float g_visit[(size_t)T_STEPS * HD];     // 8 MB
__device__ float g_gi[(size_t)T_STEPS * G3];        // 25 MB
__device__ float g_hs[(size_t)T_STEPS * HD];        // 8 MB (data + epilogue history)
__device__ unsigned g_cnt[T_STEPS];                 // per-step ready counters
__device__ float g_logits[T_STEPS];
__device__ float g_alpha[T_STEPS];

// ---------------- generic fp32 SIMT GEMM: C[M,N] = A x B (+bias) ----------------
template <bool A_KMAJ, bool B_KMAJ, bool BIAS>
__global__ __launch_bounds__(256)
void gemm_kernel(const float* __restrict__ A, const float* __restrict__ B,
                 const float* __restrict__ bias, float* __restrict__ C,
                 int M, int N, int K, int lda, int ldb, int ldc)
{
    constexpr int BM = 128, BN = 64, BK = 16;
    __shared__ float As[BK][BM + 4];
    __shared__ float Bs[BK][BN + 4];

    const int tid = threadIdx.x;
    const int tx  = tid & 15;
    const int ty  = tid >> 4;
    const int m0  = blockIdx.y * BM;
    const int n0  = blockIdx.x * BN;

    float acc[8][4];
#pragma unroll
    for (int i = 0; i < 8; i++)
#pragma unroll
        for (int j = 0; j < 4; j++) acc[i][j] = 0.f;

    for (int k0 = 0; k0 < K; k0 += BK) {
        if (A_KMAJ) {
#pragma unroll
            for (int it = 0; it < 2; it++) {
                int idx = tid + it * 256;
                int kk  = idx >> 5;
                int mm4 = idx & 31;
                float4 v = *(const float4*)&A[(size_t)(k0 + kk) * lda + m0 + mm4 * 4];
                *(float4*)&As[kk][mm4 * 4] = v;
            }
        } else {
#pragma unroll
            for (int it = 0; it < 2; it++) {
                int idx = tid + it * 256;
                int mm  = idx >> 2;
                int k4  = idx & 3;
                float4 v = *(const float4*)&A[(size_t)(m0 + mm) * lda + k0 + k4 * 4];
                As[k4 * 4 + 0][mm] = v.x;
                As[k4 * 4 + 1][mm] = v.y;
                As[k4 * 4 + 2][mm] = v.z;
                As[k4 * 4 + 3][mm] = v.w;
            }
        }
        if (B_KMAJ) {
            int kk  = tid >> 4;
            int nn4 = tid & 15;
            float4 v = *(const float4*)&B[(size_t)(k0 + kk) * ldb + n0 + nn4 * 4];
            *(float4*)&Bs[kk][nn4 * 4] = v;
        } else {
            int nn = tid >> 2;
            int k4 = tid & 3;
            float4 v = *(const float4*)&B[(size_t)(nn + n0) * ldb + k0 + k4 * 4];
            Bs[k4 * 4 + 0][nn] = v.x;
            Bs[k4 * 4 + 1][nn] = v.y;
            Bs[k4 * 4 + 2][nn] = v.z;
            Bs[k4 * 4 + 3][nn] = v.w;
        }
        __syncthreads();

#pragma unroll
        for (int kk = 0; kk < BK; kk++) {
            float4 a0 = *(const float4*)&As[kk][ty * 8];
            float4 a1 = *(const float4*)&As[kk][ty * 8 + 4];
            float4 b0 = *(const float4*)&Bs[kk][tx * 4];
            float a[8] = {a0.x, a0.y, a0.z, a0.w, a1.x, a1.y, a1.z, a1.w};
            float b[4] = {b0.x, b0.y, b0.z, b0.w};
#pragma unroll
            for (int i = 0; i < 8; i++)
#pragma unroll
                for (int j = 0; j < 4; j++) acc[i][j] += a[i] * b[j];
        }
        __syncthreads();
    }

    float4 bv = make_float4(0.f, 0.f, 0.f, 0.f);
    if (BIAS) bv = *(const float4*)&bias[n0 + tx * 4];
#pragma unroll
    for (int i = 0; i < 8; i++) {
        int m = m0 + ty * 8 + i;
        float4 v;
        v.x = acc[i][0] + bv.x;
        v.y = acc[i][1] + bv.y;
        v.z = acc[i][2] + bv.z;
        v.w = acc[i][3] + bv.w;
        *(float4*)&C[(size_t)m * ldc + n0 + tx * 4] = v;
    }
}

// ---------------- zero step counters (every replay) ----------------
__global__ __launch_bounds__(1024)
void zero_cnt_kernel()
{
    int i = blockIdx.x * 1024 + threadIdx.x;
    if (i < T_STEPS) g_cnt[i] = 0u;
}

// ---------------- PTX helpers ----------------
__device__ __forceinline__ unsigned ld_acquire_gpu(const unsigned* p)
{
    unsigned v;
    asm volatile("ld.acquire.gpu.global.u32 %0, [%1];" : "=r"(v) : "l"(p) : "memory");
    return v;
}
__device__ __forceinline__ void red_release_add(unsigned* p)
{
    asm volatile("red.release.gpu.global.add.u32 [%0], 1;" :: "l"(p) : "memory");
}
__device__ __forceinline__ float tanh_fast(float x)
{
    float e = __expf(2.f * x);
    return 1.f - 2.f / (e + 1.f);
}

// ---------------- GRU scan v9: minimal-poller counter sync, register weights --
// 64 CTAs x 8 warps; warp w of CTA c owns j = c*8 + w (3 W_hh rows in regs,
// 48 floats/lane). Sync per step (grid.sync pattern, proven in round 1):
//   produce: lane0s store h_t weakly -> __syncthreads -> tid0 red.release +1
//            (cumulativity carries the CTA's 8 stores; 64 increments/step).
//   consume: tid0 ld.acquire-polls g_cnt[t-1] >= 64 (ONLY 64 polling threads
//            on the whole chip -> LSU/L1tex queues stay empty; producer STGs
//            and real loads are never stuck behind spin loads) ->
//            __syncthreads -> every thread bulk-loads its own 16-float h
//            segment with 4 independent LDG.128 (no SMEM hop).
__global__ __launch_bounds__(256)
void gru_scan9_kernel(const float* __restrict__ W_hh, const float* __restrict__ b_hh,
                      const float* __restrict__ gi)
{
    const int tid  = threadIdx.x;
    const int w    = tid >> 5;
    const int lane = tid & 31;
    const int j    = blockIdx.x * 8 + w;

    // --- weights into registers (once) ---
    float4 wr4[4], wz4[4], wn4[4];
    {
        const float4* pr = (const float4*)(W_hh + (size_t)j * HD)            + lane * 4;
        const float4* pz = (const float4*)(W_hh + (size_t)(HD + j) * HD)     + lane * 4;
        const float4* pn = (const float4*)(W_hh + (size_t)(2 * HD + j) * HD) + lane * 4;
#pragma unroll
        for (int q = 0; q < 4; q++) { wr4[q] = pr[q]; wz4[q] = pz[q]; wn4[q] = pn[q]; }
    }
    float bhr = 0.f, bhz = 0.f, bhn = 0.f;
    if (lane == 0) {
        bhr = __ldg(b_hh + j);
        bhz = __ldg(b_hh + HD + j);
        bhn = __ldg(b_hh + 2 * HD + j);
    }

    // gi prefetch for t=0 (lane0)
    float gr = 0.f, gz = 0.f, gn = 0.f;
    if (lane == 0) {
        gr = __ldg(gi + j);
        gz = __ldg(gi + HD + j);
        gn = __ldg(gi + 2 * HD + j);
    }

    for (int t = 0; t < T_STEPS; t++) {
        // prefetch next step's gi (independent; flies during sync/compute)
        float grn = 0.f, gzn = 0.f, gnn = 0.f;
        if (lane == 0 && t + 1 < T_STEPS) {
            const float* gt = gi + (size_t)(t + 1) * G3;
            grn = __ldg(gt + j);
            gzn = __ldg(gt + HD + j);
            gnn = __ldg(gt + 2 * HD + j);
        }

        // --- acquire h_{t-1} ---
        float4 h0, h1, h2, h3;
        float hj = 0.f;
        if (t == 0) {
            h0 = h1 = h2 = h3 = make_float4(0.f, 0.f, 0.f, 0.f);
        } else {
            if (tid == 0) {
                while (ld_acquire_gpu(&g_cnt[t - 1]) < (unsigned)NCTAS) { }
            }
            __syncthreads();   // broadcast the acquire to the whole CTA
            const float4* hp = (const float4*)(g_hs + (size_t)(t - 1) * HD) + lane * 4;
            h0 = hp[0]; h1 = hp[1]; h2 = hp[2]; h3 = hp[3];   // MLP-4
            if (lane == 0) hj = g_hs[(size_t)(t - 1) * HD + j];
        }

        // --- three 512-dots, 16 h elems per lane, weights in regs ---
        float ar = 0.f, az = 0.f, an = 0.f;
        {
            float4 hh[4] = {h0, h1, h2, h3};
#pragma unroll
            for (int q = 0; q < 4; q++) {
                ar += hh[q].x * wr4[q].x + hh[q].y * wr4[q].y
                    + hh[q].z * wr4[q].z + hh[q].w * wr4[q].w;
                az += hh[q].x * wz4[q].x + hh[q].y * wz4[q].y
                    + hh[q].z * wz4[q].z + hh[q].w * wz4[q].w;
                an += hh[q].x * wn4[q].x + hh[q].y * wn4[q].y
                    + hh[q].z * wn4[q].z + hh[q].w * wn4[q].w;
            }
        }
        // packed butterfly: (ar,az) share one 64-bit shuffle chain
        double pk;
        {
            float2 t2 = make_float2(ar, az);
            pk = *reinterpret_cast<double*>(&t2);
        }
#pragma unroll
        for (int o = 16; o > 0; o >>= 1) {
            double po = __shfl_xor_sync(0xffffffffu, pk, o);
            float2 a2 = *reinterpret_cast<float2*>(&pk);
            float2 b2 = *reinterpret_cast<float2*>(&po);
            a2.x += b2.x; a2.y += b2.y;
            pk = *reinterpret_cast<double*>(&a2);
            an += __shfl_xor_sync(0xffffffffu, an, o);
        }
        {
            float2 a2 = *reinterpret_cast<float2*>(&pk);
            ar = a2.x; az = a2.y;
        }

        // --- gates + weak store on lane0 ---
        if (lane == 0) {
            float r  = 1.f / (1.f + __expf(-(gr + ar + bhr)));
            float z  = 1.f / (1.f + __expf(-(gz + az + bhz)));
            float nv = tanh_fast(gn + r * (an + bhn));
            float hn = (1.f - z) * nv + z * hj;
            g_hs[(size_t)t * HD + j] = hn;
        }
        __syncthreads();                 // CTA's 8 stores happen-before tid0
        if (tid == 0) {
            red_release_add(&g_cnt[t]);  // release carries the observed stores
        }

        gr = grn; gz = gzn; gn = gnn;
    }
}

// ---------------- logits[t] = dot(hs[t], w_att) ----------------
__global__ __launch_bounds__(256)
void logits_kernel(const float* __restrict__ w_att)
{
    __shared__ float watt[HD];
    const int tid  = threadIdx.x;
    const int w    = tid >> 5;
    const int lane = tid & 31;
    watt[tid]       = w_att[tid];
    watt[tid + 256] = w_att[tid + 256];
    __syncthreads();

    int t = blockIdx.x * 8 + w;
    const float* h = g_hs + (size_t)t * HD;
    float acc = 0.f;
    int base = lane * 16;
#pragma unroll
    for (int i = 0; i < 16; i += 4) {
        float4 hv = *(const float4*)&h[base + i];
        float4 wv = *(const float4*)&watt[base + i];
        acc += hv.x * wv.x + hv.y * wv.y + hv.z * wv.z + hv.w * wv.w;
    }
#pragma unroll
    for (int off = 16; off > 0; off >>= 1)
        acc += __shfl_down_sync(0xffffffffu, acc, off);
    if (lane == 0) g_logits[t] = acc;
}

// ---------------- softmax over 4096 logits; also zero d_out ----------------
__global__ __launch_bounds__(1024)
void softmax_kernel(float* __restrict__ out)
{
    __shared__ float red[32];
    const int tid  = threadIdx.x;
    const int lane = tid & 31;
    const int wrp  = tid >> 5;

    float m = -1e30f;
    for (int i = tid; i < T_STEPS; i += 1024) m = fmaxf(m, g_logits[i]);
#pragma unroll
    for (int o = 16; o > 0; o >>= 1) m = fmaxf(m, __shfl_xor_sync(0xffffffffu, m, o));
    if (lane == 0) red[wrp] = m;
    __syncthreads();
    if (wrp == 0) {
        float v = red[lane];
#pragma unroll
        for (int o = 16; o > 0; o >>= 1) v = fmaxf(v, __shfl_xor_sync(0xffffffffu, v, o));
        if (lane == 0) red[0] = v;
    }
    __syncthreads();
    m = red[0];
    __syncthreads();

    float s = 0.f;
    for (int i = tid; i < T_STEPS; i += 1024) {
        float e = __expf(g_logits[i] - m);
        g_alpha[i] = e;
        s += e;
    }
#pragma unroll
    for (int o = 16; o > 0; o >>= 1) s += __shfl_xor_sync(0xffffffffu, s, o);
    if (lane == 0) red[wrp] = s;
    __syncthreads();
    if (wrp == 0) {
        float v = red[lane];
#pragma unroll
        for (int o = 16; o > 0; o >>= 1) v += __shfl_xor_sync(0xffffffffu, v, o);
        if (lane == 0) red[0] = v;
    }
    __syncthreads();
    float inv = 1.f / red[0];
    for (int i = tid; i < T_STEPS; i += 1024) g_alpha[i] *= inv;

    if (tid < HD) out[tid] = 0.f;
}

// ---------------- out[d] += sum_t alpha[t] * hs[t][d] ----------------
__global__ __launch_bounds__(256)
void wsum_kernel(float* __restrict__ out)
{
    const int tid = threadIdx.x;
    const int d   = tid * 2;
    float ax = 0.f, ay = 0.f;
    int t0 = blockIdx.x * 64;
#pragma unroll 4
    for (int tt = 0; tt < 64; tt++) {
        int t = t0 + tt;
        float a = g_alpha[t];
        float2 hv = *(const float2*)&g_hs[(size_t)t * HD + d];
        ax += a * hv.x;
        ay += a * hv.y;
    }
    atomicAdd(out + d, ax);
    atomicAdd(out + d + 1, ay);
}

// ---------------- launcher ----------------
extern "C" void kernel_launch(void* const* d_in, const int* in_sizes, int n_in,
                              void* d_out, int out_size)
{
    const float* H     = (const float*)d_in[0];
    // d_in[1] = TE (unused)
    const float* X_emb = (const float*)d_in[2];
    const float* W_ih  = (const float*)d_in[3];
    const float* W_hh  = (const float*)d_in[4];
    const float* b_ih  = (const float*)d_in[5];
    const float* b_hh  = (const float*)d_in[6];
    const float* w_att = (const float*)d_in[7];
    float* out = (float*)d_out;

    float* visit; float* gi;
    cudaGetSymbolAddress((void**)&visit, g_visit);
    cudaGetSymbolAddress((void**)&gi, g_gi);

    // 0) zero the per-step ready counters
    zero_cnt_kernel<<<(T_STEPS + 1023) / 1024, 1024>>>();
    // 1) visit_emb[4096,512] = H^T @ X_emb
    {
        dim3 grid(HD / 64, T_STEPS / 128);
        gemm_kernel<true, true, false><<<grid, 256>>>(
            H, X_emb, nullptr, visit, T_STEPS, HD, NC, T_STEPS, HD, HD);
    }
    // 2) gi[4096,1536] = visit_emb @ W_ih^T + b_ih
    {
        dim3 grid(G3 / 64, T_STEPS / 128);
        gemm_kernel<false, false, true><<<grid, 256>>>(
            visit, W_ih, b_ih, gi, T_STEPS, G3, HD, HD, HD, G3);
    }
    // 3) sequential GRU scan (minimal-poller counter sync)
    gru_scan9_kernel<<<NCTAS, 256>>>(W_hh, b_hh, gi);
    // 4) attention logits
    logits_kernel<<<T_STEPS / 8, 256>>>(w_att);
    // 5) softmax (+ zero out)
    softmax_kernel<<<1, 1024>>>(out);
    // 6) weighted sum
    wsum_kernel<<<T_STEPS / 64, 256>>>(out);
}